// round 14
// baseline (speedup 1.0000x reference)
#include <cuda_runtime.h>
#include <math.h>
#include <stdint.h>

// Problem constants
#define B_  2
#define S_  2048
#define D_  1024
#define H_  16
#define L_  512
#define DH_ 64
#define NTOK (B_*S_)          // 4096
#define HL_ (H_*L_)           // 8192

// ---------------- scratch (device globals) --------------------------------------
__device__ float g_c    [NTOK * L_];                 // pre-LN latent (exact fp32)
__device__ float g_ckv  [NTOK * L_];                 // LN latent, tf32 bits
__device__ float g_akT  [L_ * D_];                   // absorbed K^T [L,D], tf32
__device__ float g_tmp  [(size_t)B_ * S_ * H_ * L_]; // q_eff, tf32
__device__ float g_vT   [(size_t)D_ * NTOK];         // V^T [D,NTOK], tf32
__device__ float g_ctx  [NTOK * D_];                 // context, tf32
__device__ float g_xtf  [NTOK * D_];                 // x, tf32
__device__ float g_wdkv [L_ * D_];                   // W_dkv, tf32
__device__ float g_wq   [D_ * D_];                   // W_q, tf32
__device__ float g_wukT [L_ * D_];                   // W_uk^T [L,D], tf32
__device__ float g_wuv  [D_ * L_];                   // W_uv, tf32
__device__ float g_wo   [D_ * D_];                   // W_o, tf32

// ---------------- helpers ---------------------------------------------------------
__device__ __forceinline__ uint32_t s2u(const void* p) {
    uint32_t a;
    asm("{ .reg .u64 t; cvta.to.shared.u64 t, %1; cvt.u32.u64 %0, t; }"
        : "=r"(a) : "l"(p));
    return a;
}
__device__ __forceinline__ unsigned f2tf(float f) {
    unsigned u;
    asm("cvt.rna.tf32.f32 %0, %1;" : "=r"(u) : "f"(f));
    return u;
}
__device__ __forceinline__ float f2tff(float f) {
    return __uint_as_float(f2tf(f));
}
__device__ __forceinline__ void cp16(uint32_t dst, const void* src) {
    asm volatile("cp.async.cg.shared.global [%0], [%1], 16;"
                 :: "r"(dst), "l"(src) : "memory");
}
__device__ __forceinline__ void ldm_x4(unsigned &r0, unsigned &r1, unsigned &r2,
                                       unsigned &r3, uint32_t addr) {
    asm volatile("ldmatrix.sync.aligned.m8n8.x4.shared.b16 {%0,%1,%2,%3}, [%4];"
                 : "=r"(r0), "=r"(r1), "=r"(r2), "=r"(r3) : "r"(addr));
}
__device__ __forceinline__ void mma_tf32(float (&c)[4], const unsigned (&a)[4],
                                         const unsigned (&b)[2]) {
    asm volatile(
        "mma.sync.aligned.m16n8k8.row.col.f32.tf32.tf32.f32 "
        "{%0,%1,%2,%3}, {%4,%5,%6,%7}, {%8,%9}, {%0,%1,%2,%3};"
        : "+f"(c[0]), "+f"(c[1]), "+f"(c[2]), "+f"(c[3])
        : "r"(a[0]), "r"(a[1]), "r"(a[2]), "r"(a[3]), "r"(b[0]), "r"(b[1]));
}

// ---------------- tf32 mma.sync GEMM (single-sync 3-stage cp.async) ----------------
template<int BN, bool CT, bool TFOUT>
__global__ __launch_bounds__(256, 2)
void tc_gemm(const float* __restrict__ A, const float* __restrict__ B,
             float* __restrict__ C,
             int M, int N, int K, int lda, int ldb, int ldc,
             long sA1, long sA2, long sB1, long sB2, long sC1, long sC2,
             int zdiv, float alpha)
{
    constexpr int BM = 128, BK = 32, STAGES = 3;
    constexpr int MT = 4, NT = BN / 32, NG = NT / 2;
    constexpr int LA = BM * 8 / 256;
    constexpr int LB = BN * 8 / 256;
    constexpr int STG_B = (BM + BN) * 128;

    extern __shared__ __align__(128) char sm[];
    const uint32_t smu = s2u(sm);

    const int z = blockIdx.z;
    const int zhi = z / zdiv, zlo = z % zdiv;
    A += (long)zhi * sA1 + (long)zlo * sA2;
    B += (long)zhi * sB1 + (long)zlo * sB2;
    C += (long)zhi * sC1 + (long)zlo * sC2;

    const int m0 = blockIdx.y * BM;
    const int n0 = blockIdx.x * BN;

    const int tid  = threadIdx.x;
    const int warp = tid >> 5;
    const int lane = tid & 31;
    const int gid  = lane >> 2;
    const int tig  = lane & 3;
    const int wm0  = (warp & 1) * 64;
    const int wn0  = (warp >> 1) * (BN / 4);

    const uint32_t lrow  = ((lane >> 3) & 1) * 8 + (lane & 7);
    const uint32_t chsel = (lane >> 4);
    const uint32_t swl   = lane & 7;
    const uint32_t aRow = (wm0 + lrow) * 128;
    const uint32_t bRow = (wn0 + lrow) * 128;

    int ar[LA]; uint32_t ad[LA]; int aco[LA];
    #pragma unroll
    for (int i = 0; i < LA; i++) {
        int f = tid + i * 256, row = f >> 3, ch = f & 7;
        ar[i] = row; aco[i] = ch * 4;
        ad[i] = row * 128 + ((ch ^ (row & 7)) << 4);
    }
    int br[LB]; uint32_t bd[LB]; int bco[LB];
    #pragma unroll
    for (int i = 0; i < LB; i++) {
        int f = tid + i * 256, row = f >> 3, ch = f & 7;
        br[i] = row; bco[i] = ch * 4;
        bd[i] = BM * 128 + row * 128 + ((ch ^ (row & 7)) << 4);
    }

    float acc[MT][NT][4];
    #pragma unroll
    for (int i = 0; i < MT; i++)
        #pragma unroll
        for (int j = 0; j < NT; j++)
            #pragma unroll
            for (int r = 0; r < 4; r++) acc[i][j][r] = 0.f;

    const int T = K / BK;

    auto issue_stage = [&](int t) {
        const int k0 = t * BK;
        const uint32_t sb = smu + (t % STAGES) * STG_B;
        #pragma unroll
        for (int i = 0; i < LA; i++)
            cp16(sb + ad[i], &A[(long)(m0 + ar[i]) * lda + k0 + aco[i]]);
        #pragma unroll
        for (int i = 0; i < LB; i++)
            cp16(sb + bd[i], &B[(long)(n0 + br[i]) * ldb + k0 + bco[i]]);
        asm volatile("cp.async.commit_group;" ::: "memory");
    };

    int fetch = 0;
    #pragma unroll
    for (int s = 0; s < STAGES - 1; s++)
        if (fetch < T) { issue_stage(fetch); fetch++; }

    for (int t = 0; t < T; t++) {
        if (t == T - 1)
            asm volatile("cp.async.wait_group 0;" ::: "memory");
        else
            asm volatile("cp.async.wait_group %0;" :: "n"(STAGES - 2) : "memory");
        __syncthreads();
        if (fetch < T) { issue_stage(fetch); fetch++; }

        const uint32_t sb  = smu + (t % STAGES) * STG_B;
        const uint32_t sbB = sb + BM * 128;
        #pragma unroll
        for (int ks = 0; ks < 4; ks++) {
            const uint32_t chx = (((2u * ks + chsel) ^ swl) << 4);
            unsigned a[MT][4];
            #pragma unroll
            for (int mt = 0; mt < MT; mt++)
                ldm_x4(a[mt][0], a[mt][1], a[mt][2], a[mt][3],
                       sb + aRow + mt * 16 * 128 + chx);
            unsigned b[NT][2];
            #pragma unroll
            for (int ng = 0; ng < NG; ng++) {
                unsigned q0, q1, q2, q3;
                ldm_x4(q0, q1, q2, q3, sbB + bRow + ng * 16 * 128 + chx);
                b[2*ng  ][0] = q0; b[2*ng  ][1] = q2;
                b[2*ng+1][0] = q1; b[2*ng+1][1] = q3;
            }
            #pragma unroll
            for (int mt = 0; mt < MT; mt++)
                #pragma unroll
                for (int nt = 0; nt < NT; nt++)
                    mma_tf32(acc[mt][nt], a[mt], b[nt]);
        }
    }

    #pragma unroll
    for (int mt = 0; mt < MT; mt++) {
        int r0 = m0 + wm0 + mt * 16 + gid;
        #pragma unroll
        for (int nt = 0; nt < NT; nt++) {
            int cc = n0 + wn0 + nt * 8 + tig * 2;
            float o0 = acc[mt][nt][0] * alpha, o1 = acc[mt][nt][1] * alpha;
            float o2 = acc[mt][nt][2] * alpha, o3 = acc[mt][nt][3] * alpha;
            if (TFOUT) { o0 = f2tff(o0); o1 = f2tff(o1); o2 = f2tff(o2); o3 = f2tff(o3); }
            if (CT) {
                C[(long)(cc    ) * ldc + r0    ] = o0;
                C[(long)(cc + 1) * ldc + r0    ] = o1;
                C[(long)(cc    ) * ldc + r0 + 8] = o2;
                C[(long)(cc + 1) * ldc + r0 + 8] = o3;
            } else {
                *(float2*)&C[(long)r0 * ldc + cc]       = make_float2(o0, o1);
                *(float2*)&C[(long)(r0 + 8) * ldc + cc] = make_float2(o2, o3);
            }
        }
    }
}

// ---------------- fused causal flash attention, 512 threads ------------------------
// Same algorithm as R9, remapped to 16 warps (4 M-warps x 32 rows, 4 N-warps).
// Per-thread accumulators halve -> ~120 regs -> full 16-warp occupancy at 1 CTA.
#define ATT_PV   (3 * 32768)            // P offset (bytes)
#define ATT_VV   (ATT_PV + 65536)       // V offset
#define ATT_RED  (ATT_VV + 32768)       // redbuf offset (2 x 4 x 128 floats)
#define ATT_SMEM (ATT_RED + 4096)

__global__ __launch_bounds__(512, 1)
void attn_k(const float* __restrict__ qe, const float* __restrict__ ckv,
            const float* __restrict__ vT, float* __restrict__ ctx)
{
    extern __shared__ __align__(128) char sm[];
    const uint32_t smu = s2u(sm);
    float* red0 = (float*)(sm + ATT_RED);
    float* red1 = red0 + 512;

    const int qi = 15 - blockIdx.x;              // heavy tiles first
    const int bh = blockIdx.y;
    const int b  = bh >> 4, h = bh & 15;
    const int m0 = qi * 128;

    const float* Aq = qe  + (size_t)b * S_ * HL_ + (size_t)h * L_;
    const float* Bc = ckv + (size_t)b * S_ * L_;
    const float* Vv = vT  + (size_t)(h * 64) * NTOK + (size_t)b * S_;
    float*       Co = ctx + (size_t)b * S_ * D_ + h * 64;

    const int tid  = threadIdx.x;
    const int warp = tid >> 5;                    // 0..15
    const int lane = tid & 31;
    const int gid  = lane >> 2;
    const int tig  = lane & 3;
    const int wm0  = (warp & 3) * 32;             // 4 M-warps x 32 rows
    const int nw   = warp >> 2;                   // 4 N-warp groups
    const int wn0  = nw * 32;                     // QK cols
    const int wn0v = nw * 16;                     // PV d-cols

    const uint32_t lrow  = ((lane >> 3) & 1) * 8 + (lane & 7);
    const uint32_t chsel = (lane >> 4);
    const uint32_t swl   = lane & 7;
    const uint32_t aRow  = (wm0 + lrow) * 128;
    const uint32_t bRow  = (wn0 + lrow) * 128;
    const uint32_t vRow  = (wn0v + lrow) * 128;

    // cp.async coords: 128x32 tile = 1024 16B-chunks, 2 per thread
    int ar2[2]; uint32_t ad2[2]; int aco2[2];
    #pragma unroll
    for (int i = 0; i < 2; i++) {
        int f = tid + i * 512, row = f >> 3, ch = f & 7;
        ar2[i] = row; aco2[i] = ch * 4;
        ad2[i] = row * 128 + ((ch ^ (row & 7)) << 4);
    }

    float acc2[2][2][4];                          // [mt][ntv][slot]
    float mrow[2][2], lsum[2][2];
    #pragma unroll
    for (int mt = 0; mt < 2; mt++)
        #pragma unroll
        for (int hf = 0; hf < 2; hf++) {
            mrow[mt][hf] = -1e30f; lsum[mt][hf] = 0.f;
        }
    #pragma unroll
    for (int mt = 0; mt < 2; mt++)
        #pragma unroll
        for (int ntv = 0; ntv < 2; ntv++)
            #pragma unroll
            for (int r = 0; r < 4; r++) acc2[mt][ntv][r] = 0.f;

    for (int j = 0; j <= qi; j++) {
        const int t0 = j * 128;

        // ---- V tile cp.async (64 d-rows x 128 t): 2048 chunks, 4/thread ----
        #pragma unroll
        for (int i = 0; i < 4; i++) {
            int f = tid + i * 512;
            int kt = f >> 9, w = f & 511, row = w >> 3, ch = w & 7;
            cp16(smu + ATT_VV + kt * 8192 + row * 128 + ((ch ^ (row & 7)) << 4),
                 Vv + (size_t)row * NTOK + t0 + kt * 32 + ch * 4);
        }
        asm volatile("cp.async.commit_group;" ::: "memory");

        // ---- QK^T: K=512, 16 k-tiles, 3-stage ----
        float acc1[2][4][4];
        #pragma unroll
        for (int mt = 0; mt < 2; mt++)
            #pragma unroll
            for (int nt = 0; nt < 4; nt++)
                #pragma unroll
                for (int r = 0; r < 4; r++) acc1[mt][nt][r] = 0.f;

        auto issue_qk = [&](int t) {
            const int k0 = t * 32;
            const uint32_t sb = smu + (t % 3) * 32768;
            #pragma unroll
            for (int i = 0; i < 2; i++)
                cp16(sb + ad2[i], &Aq[(size_t)(m0 + ar2[i]) * HL_ + k0 + aco2[i]]);
            #pragma unroll
            for (int i = 0; i < 2; i++)
                cp16(sb + 16384 + ad2[i], &Bc[(size_t)(t0 + ar2[i]) * L_ + k0 + aco2[i]]);
            asm volatile("cp.async.commit_group;" ::: "memory");
        };

        issue_qk(0); issue_qk(1);
        for (int t = 0; t < 16; t++) {
            if (t == 15) asm volatile("cp.async.wait_group 0;" ::: "memory");
            else         asm volatile("cp.async.wait_group 1;" ::: "memory");
            __syncthreads();
            if (t + 2 < 16) issue_qk(t + 2);

            const uint32_t sb  = smu + (t % 3) * 32768;
            const uint32_t sbB = sb + 16384;
            #pragma unroll
            for (int ks = 0; ks < 4; ks++) {
                const uint32_t chx = (((2u * ks + chsel) ^ swl) << 4);
                unsigned a[2][4];
                #pragma unroll
                for (int mt = 0; mt < 2; mt++)
                    ldm_x4(a[mt][0], a[mt][1], a[mt][2], a[mt][3],
                           sb + aRow + mt * 16 * 128 + chx);
                unsigned bb[4][2];
                #pragma unroll
                for (int ng = 0; ng < 2; ng++) {
                    unsigned q0, q1, q2, q3;
                    ldm_x4(q0, q1, q2, q3, sbB + bRow + ng * 16 * 128 + chx);
                    bb[2*ng  ][0] = q0; bb[2*ng  ][1] = q2;
                    bb[2*ng+1][0] = q1; bb[2*ng+1][1] = q3;
                }
                #pragma unroll
                for (int mt = 0; mt < 2; mt++)
                    #pragma unroll
                    for (int nt = 0; nt < 4; nt++)
                        mma_tf32(acc1[mt][nt], a[mt], bb[nt]);
            }
        }

        // ---- scale + causal mask (diagonal tile only) ----
        #pragma unroll
        for (int mt = 0; mt < 2; mt++)
            #pragma unroll
            for (int nt = 0; nt < 4; nt++)
                #pragma unroll
                for (int r = 0; r < 4; r++) {
                    float v = acc1[mt][nt][r] * 0.125f;
                    if (j == qi) {
                        int row = m0 + wm0 + mt * 16 + gid + (r >> 1) * 8;
                        int col = t0 + wn0 + nt * 8 + tig * 2 + (r & 1);
                        if (col > row) v = -1e30f;
                    }
                    acc1[mt][nt][r] = v;
                }

        // ---- row max: shfl over tig, smem over 4 n-warp groups ----
        #pragma unroll
        for (int mt = 0; mt < 2; mt++)
            #pragma unroll
            for (int hf = 0; hf < 2; hf++) {
                float v = -1e30f;
                #pragma unroll
                for (int nt = 0; nt < 4; nt++)
                    v = fmaxf(v, fmaxf(acc1[mt][nt][hf*2], acc1[mt][nt][hf*2+1]));
                v = fmaxf(v, __shfl_xor_sync(0xffffffffu, v, 1));
                v = fmaxf(v, __shfl_xor_sync(0xffffffffu, v, 2));
                if (tig == 0) red0[nw * 128 + wm0 + mt * 16 + gid + hf * 8] = v;
            }
        __syncthreads();

        float mnew[2][2], scl[2][2];
        #pragma unroll
        for (int mt = 0; mt < 2; mt++)
            #pragma unroll
            for (int hf = 0; hf < 2; hf++) {
                int row = wm0 + mt * 16 + gid + hf * 8;
                float g = fmaxf(fmaxf(red0[row], red0[128 + row]),
                                fmaxf(red0[256 + row], red0[384 + row]));
                float mn = fmaxf(mrow[mt][hf], g);
                mnew[mt][hf] = mn;
                scl[mt][hf]  = __expf(mrow[mt][hf] - mn);
                mrow[mt][hf] = mn;
            }

        // ---- exp, P->smem (tf32, A-tile format), row sums ----
        unsigned* smw = (unsigned*)sm;
        float rsum[2][2] = {};
        #pragma unroll
        for (int mt = 0; mt < 2; mt++)
            #pragma unroll
            for (int nt = 0; nt < 4; nt++) {
                int col = wn0 + nt * 8 + tig * 2;
                int kt = col >> 5, c32 = col & 31;
                uint32_t base = (ATT_PV >> 2) + kt * 4096;
                #pragma unroll
                for (int hf = 0; hf < 2; hf++) {
                    float p0 = __expf(acc1[mt][nt][hf*2  ] - mnew[mt][hf]);
                    float p1 = __expf(acc1[mt][nt][hf*2+1] - mnew[mt][hf]);
                    rsum[mt][hf] += p0 + p1;
                    int row = wm0 + mt * 16 + gid + hf * 8;
                    uint32_t idx = base + row * 32 +
                                   (((c32 >> 2) ^ (row & 7)) << 2) + (c32 & 3);
                    uint2 u = make_uint2(f2tf(p0), f2tf(p1));
                    *(uint2*)&smw[idx] = u;
                }
            }
        #pragma unroll
        for (int mt = 0; mt < 2; mt++)
            #pragma unroll
            for (int hf = 0; hf < 2; hf++) {
                float s = rsum[mt][hf];
                s += __shfl_xor_sync(0xffffffffu, s, 1);
                s += __shfl_xor_sync(0xffffffffu, s, 2);
                if (tig == 0) red1[nw * 128 + wm0 + mt * 16 + gid + hf * 8] = s;
                #pragma unroll
                for (int ntv = 0; ntv < 2; ntv++) {
                    acc2[mt][ntv][hf*2  ] *= scl[mt][hf];
                    acc2[mt][ntv][hf*2+1] *= scl[mt][hf];
                }
            }
        __syncthreads();
        #pragma unroll
        for (int mt = 0; mt < 2; mt++)
            #pragma unroll
            for (int hf = 0; hf < 2; hf++) {
                int row = wm0 + mt * 16 + gid + hf * 8;
                float g = red1[row] + red1[128 + row] + red1[256 + row] + red1[384 + row];
                lsum[mt][hf] = lsum[mt][hf] * scl[mt][hf] + g;
            }

        // ---- PV: 4 k-subtiles of 32 ----
        #pragma unroll
        for (int kt = 0; kt < 4; kt++) {
            const uint32_t pB = smu + ATT_PV + kt * 16384;
            const uint32_t vB = smu + ATT_VV + kt * 8192;
            #pragma unroll
            for (int ks = 0; ks < 4; ks++) {
                const uint32_t chx = (((2u * ks + chsel) ^ swl) << 4);
                unsigned a[2][4];
                #pragma unroll
                for (int mt = 0; mt < 2; mt++)
                    ldm_x4(a[mt][0], a[mt][1], a[mt][2], a[mt][3],
                           pB + aRow + mt * 16 * 128 + chx);
                unsigned bb[2][2];
                {
                    unsigned q0, q1, q2, q3;
                    ldm_x4(q0, q1, q2, q3, vB + vRow + chx);
                    bb[0][0] = q0; bb[0][1] = q2;
                    bb[1][0] = q1; bb[1][1] = q3;
                }
                #pragma unroll
                for (int mt = 0; mt < 2; mt++)
                    #pragma unroll
                    for (int ntv = 0; ntv < 2; ntv++)
                        mma_tf32(acc2[mt][ntv], a[mt], bb[ntv]);
            }
        }
        __syncthreads();   // protect P/V from next j's writes
    }

    // ---- epilogue: normalize, write ctx (tf32) ----
    #pragma unroll
    for (int mt = 0; mt < 2; mt++) {
        float inv0 = 1.0f / lsum[mt][0];
        float inv1 = 1.0f / lsum[mt][1];
        int r0 = m0 + wm0 + mt * 16 + gid;
        #pragma unroll
        for (int ntv = 0; ntv < 2; ntv++) {
            int cc = wn0v + ntv * 8 + tig * 2;
            float2 v0 = make_float2(f2tff(acc2[mt][ntv][0] * inv0),
                                    f2tff(acc2[mt][ntv][1] * inv0));
            float2 v1 = make_float2(f2tff(acc2[mt][ntv][2] * inv1),
                                    f2tff(acc2[mt][ntv][3] * inv1));
            *(float2*)&Co[(size_t)r0 * D_ + cc]       = v0;
            *(float2*)&Co[(size_t)(r0 + 8) * D_ + cc] = v1;
        }
    }
}

// ---------------- elementwise tf32 convert ----------------------------------------
__global__ __launch_bounds__(256)
void cvt_k(const float4* __restrict__ in, float4* __restrict__ out, int n4)
{
    int i = blockIdx.x * 256 + threadIdx.x;
    if (i < n4) {
        float4 v = in[i];
        v.x = f2tff(v.x); v.y = f2tff(v.y); v.z = f2tff(v.z); v.w = f2tff(v.w);
        out[i] = v;
    }
}

// ---------------- transpose + tf32 convert ----------------------------------------
__global__ __launch_bounds__(256)
void trcvt_k(const float* __restrict__ in, float* __restrict__ out, int R, int C)
{
    __shared__ float t[32][33];
    const int r0 = blockIdx.y * 32, c0 = blockIdx.x * 32;
    const int tx = threadIdx.x & 31, ty = threadIdx.x >> 5;
    #pragma unroll
    for (int j = 0; j < 32; j += 8)
        t[ty + j][tx] = in[(long)(r0 + ty + j) * C + c0 + tx];
    __syncthreads();
    #pragma unroll
    for (int j = 0; j < 32; j += 8)
        out[(long)(c0 + ty + j) * R + r0 + tx] = f2tff(t[tx][ty + j]);
}

// ---------------- LayerNorm over L=512 ------------------------------------------
__global__ __launch_bounds__(256)
void ln_k(const float* __restrict__ c, float* __restrict__ ckv,
          float* __restrict__ out2,
          const float* __restrict__ gamma, const float* __restrict__ beta)
{
    __shared__ float red[256];
    const int r   = blockIdx.x;
    const int tid = threadIdx.x;
    const float* row = c + (long)r * L_;

    float a0 = row[tid], a1 = row[tid + 256];

    red[tid] = a0 + a1; __syncthreads();
    for (int s = 128; s > 0; s >>= 1) { if (tid < s) red[tid] += red[tid+s]; __syncthreads(); }
    float mu = red[0] * (1.0f / L_); __syncthreads();

    float d0 = a0 - mu, d1 = a1 - mu;
    red[tid] = d0*d0 + d1*d1; __syncthreads();
    for (int s = 128; s > 0; s >>= 1) { if (tid < s) red[tid] += red[tid+s]; __syncthreads(); }
    float rstd = rsqrtf(red[0] * (1.0f / L_) + 1e-5f);

    float y0 = d0 * rstd * gamma[tid]       + beta[tid];
    float y1 = d1 * rstd * gamma[tid + 256] + beta[tid + 256];

    long o = (long)r * L_;
    ckv[o + tid] = f2tff(y0); ckv[o + tid + 256] = f2tff(y1);
    if (out2) { out2[o + tid] = y0; out2[o + tid + 256] = y1; }
}

// ---------------- launch ---------------------------------------------------------
extern "C" void kernel_launch(void* const* d_in, const int* in_sizes, int n_in,
                              void* d_out, int out_size)
{
    const float* x      = (const float*)d_in[0];
    const float* W_q    = (const float*)d_in[1];
    const float* W_dkv  = (const float*)d_in[2];
    const float* W_uk   = (const float*)d_in[3];
    const float* W_uv   = (const float*)d_in[4];
    const float* W_o    = (const float*)d_in[5];
    const float* gamma  = (const float*)d_in[6];
    const float* beta   = (const float*)d_in[7];
    float* out = (float*)d_out;

    float *c, *ckv, *akT, *tmp, *vT, *ctx;
    float *xtf, *wdkv, *wq, *wukT, *wuv, *wo;
    cudaGetSymbolAddress((void**)&c,    g_c);
    cudaGetSymbolAddress((void**)&ckv,  g_ckv);
    cudaGetSymbolAddress((void**)&akT,  g_akT);
    cudaGetSymbolAddress((void**)&tmp,  g_tmp);
    cudaGetSymbolAddress((void**)&vT,   g_vT);
    cudaGetSymbolAddress((void**)&ctx,  g_ctx);
    cudaGetSymbolAddress((void**)&xtf,  g_xtf);
    cudaGetSymbolAddress((void**)&wdkv, g_wdkv);
    cudaGetSymbolAddress((void**)&wq,   g_wq);
    cudaGetSymbolAddress((void**)&wukT, g_wukT);
    cudaGetSymbolAddress((void**)&wuv,  g_wuv);
    cudaGetSymbolAddress((void**)&wo,   g_wo);

    float* out_ckv = (out_size >= NTOK*D_ + NTOK*L_) ? out + (long)NTOK*D_ : nullptr;

    const int SM128 = 3 * (128 + 128) * 128;   // 98304 B
    cudaFuncSetAttribute(tc_gemm<128,false,false>, cudaFuncAttributeMaxDynamicSharedMemorySize, SM128);
    cudaFuncSetAttribute(tc_gemm<128,true ,true >, cudaFuncAttributeMaxDynamicSharedMemorySize, SM128);
    cudaFuncSetAttribute(tc_gemm<128,false,true >, cudaFuncAttributeMaxDynamicSharedMemorySize, SM128);
    cudaFuncSetAttribute(attn_k, cudaFuncAttributeMaxDynamicSharedMemorySize, ATT_SMEM);

    const dim3 blk(256);

    // P0: convert inputs to tf32 bit patterns
    cvt_k<<<NTOK*D_/1024, 256>>>((const float4*)x,     (float4*)xtf,  NTOK*D_/4);
    cvt_k<<<L_*D_/1024,   256>>>((const float4*)W_dkv, (float4*)wdkv, L_*D_/4);
    cvt_k<<<D_*D_/1024,   256>>>((const float4*)W_q,   (float4*)wq,   D_*D_/4);
    cvt_k<<<D_*L_/1024,   256>>>((const float4*)W_uv,  (float4*)wuv,  D_*L_/4);
    cvt_k<<<D_*D_/1024,   256>>>((const float4*)W_o,   (float4*)wo,   D_*D_/4);
    trcvt_k<<<dim3(L_/32, D_/32), 256>>>(W_uk, wukT, D_, L_);

    // K1: c = x @ W_dkv^T
    tc_gemm<128,false,false><<<dim3(L_/128, NTOK/128, 1), blk, SM128>>>(
        xtf, wdkv, c, NTOK, L_, D_, D_, D_, L_,
        0,0, 0,0, 0,0, 16, 1.0f);

    // K2: LayerNorm -> ckv (tf32) + exact second output
    ln_k<<<NTOK, 256>>>(c, ckv, out_ckv, gamma, beta);

    // K3: akT = (W_q @ W_uk)^T  [L,D]
    tc_gemm<128,true,true><<<dim3(L_/128, D_/128, 1), blk, SM128>>>(
        wq, wukT, akT, D_, L_, D_, D_, D_, D_,
        0,0, 0,0, 0,0, 16, 1.0f);

    // K4: tmp = q_eff (batched over h)
    tc_gemm<128,false,true><<<dim3(L_/128, NTOK/128, H_), blk, SM128>>>(
        xtf, akT, tmp, NTOK, L_, DH_, D_, D_, H_*L_,
        0, DH_,
        0, DH_,
        0, L_,
        16, 1.0f);

    // K7: vT = (ckv @ W_uv^T)^T  [D,NTOK]
    tc_gemm<128,true,true><<<dim3(D_/128, NTOK/128, 1), blk, SM128>>>(
        ckv, wuv, vT, NTOK, D_, L_, L_, L_, NTOK,
        0,0, 0,0, 0,0, 16, 1.0f);

    // K5+K6+K8 fused: causal flash attention -> ctx  (512 threads/CTA)
    attn_k<<<dim3(16, 32), 512, ATT_SMEM>>>(tmp, ckv, vT, ctx);

    // K9: out = ctx @ W_o^T
    tc_gemm<128,false,false><<<dim3(D_/128, NTOK/128, 1), blk, SM128>>>(
        ctx, wo, out, NTOK, D_, D_, D_, D_, D_,
        0,0, 0,0, 0,0, 16, 1.0f);
}

// round 15
// speedup vs baseline: 1.6087x; 1.6087x over previous
#include <cuda_runtime.h>
#include <cuda_fp16.h>
#include <math.h>
#include <stdint.h>

// Problem constants
#define B_  2
#define S_  2048
#define D_  1024
#define H_  16
#define L_  512
#define DH_ 64
#define NTOK (B_*S_)          // 4096
#define HL_ (H_*L_)           // 8192

// ---------------- scratch (device globals) --------------------------------------
__device__ float  g_c   [NTOK * L_];                  // pre-LN latent (exact fp32)
__device__ float  g_sc  [(size_t)B_ * H_ * S_ * S_];  // scores fp32
__device__ __half g_at  [(size_t)B_ * H_ * S_ * S_];  // attn fp16
__device__ __half g_ckv [NTOK * L_];                  // LN latent fp16
__device__ __half g_akT [L_ * D_];                    // absorbed K^T [L,D]
__device__ __half g_tmp [(size_t)B_ * S_ * H_ * L_];  // q_eff
__device__ __half g_vT  [(size_t)D_ * NTOK];          // V^T [D,NTOK]
__device__ __half g_ctx [NTOK * D_];                  // context
__device__ __half g_xh  [NTOK * D_];                  // x fp16
__device__ __half g_wdkv[L_ * D_];
__device__ __half g_wq  [D_ * D_];
__device__ __half g_wukT[L_ * D_];                    // W_uk^T [L,D]
__device__ __half g_wuv [D_ * L_];
__device__ __half g_wo  [D_ * D_];

// ---------------- helpers ---------------------------------------------------------
__device__ __forceinline__ uint32_t s2u(const void* p) {
    uint32_t a;
    asm("{ .reg .u64 t; cvta.to.shared.u64 t, %1; cvt.u32.u64 %0, t; }"
        : "=r"(a) : "l"(p));
    return a;
}
__device__ __forceinline__ void cp16(uint32_t dst, const void* src) {
    asm volatile("cp.async.cg.shared.global [%0], [%1], 16;"
                 :: "r"(dst), "l"(src) : "memory");
}
__device__ __forceinline__ void ldm_x4(unsigned &r0, unsigned &r1, unsigned &r2,
                                       unsigned &r3, uint32_t addr) {
    asm volatile("ldmatrix.sync.aligned.m8n8.x4.shared.b16 {%0,%1,%2,%3}, [%4];"
                 : "=r"(r0), "=r"(r1), "=r"(r2), "=r"(r3) : "r"(addr));
}
__device__ __forceinline__ void mma_f16(float (&c)[4], const unsigned (&a)[4],
                                        const unsigned (&b)[2]) {
    asm volatile(
        "mma.sync.aligned.m16n8k16.row.col.f32.f16.f16.f32 "
        "{%0,%1,%2,%3}, {%4,%5,%6,%7}, {%8,%9}, {%0,%1,%2,%3};"
        : "+f"(c[0]), "+f"(c[1]), "+f"(c[2]), "+f"(c[3])
        : "r"(a[0]), "r"(a[1]), "r"(a[2]), "r"(a[3]), "r"(b[0]), "r"(b[1]));
}

// ---------------- fp16 mma.sync GEMM (3-stage cp.async, BK=64) ---------------------
// C[m,n] = alpha * sum_k A[m,k] * B[n,k]   (A,B row-major K-major __half)
// CT: store transposed C[n*ldc+m]. HOUT: C is __half, else float.
// CAUSAL: 0 none, 1 skip blocks n0 > m0+BM-1, 2 clamp K to m0+BM.
// BM=128, BK=64 (128B rows, 8 x 16B chunks, XOR swizzle chunk^=(row&7)).
// 256 threads = 8 warps (2M x 4N), warp tile 64 x BN/4; 4 k16-steps per tile.
template<int BN, int CAUSAL, bool CT, bool HOUT>
__global__ __launch_bounds__(256, 2)
void hgemm(const __half* __restrict__ A, const __half* __restrict__ B,
           void* __restrict__ Cv,
           int M, int N, int K, int lda, int ldb, int ldc,
           long sA1, long sA2, long sB1, long sB2, long sC1, long sC2,
           int zdiv, float alpha)
{
    constexpr int BM = 128, BK = 64, STAGES = 3;
    constexpr int MT = 4, NT = BN / 32, NG = NT / 2;
    constexpr int LA = BM * 8 / 256;          // 16B chunks/thread for A (4)
    constexpr int LB = BN * 8 / 256;          // 4 (BN=128) or 2 (BN=64)
    constexpr int STG_B = (BM + BN) * 128;    // bytes per stage

    extern __shared__ __align__(128) char sm[];
    const uint32_t smu = s2u(sm);

    const int z = blockIdx.z;
    const int zhi = z / zdiv, zlo = z % zdiv;
    A += (long)zhi * sA1 + (long)zlo * sA2;
    B += (long)zhi * sB1 + (long)zlo * sB2;
    float*  Cf = (float*) Cv + ((long)zhi * sC1 + (long)zlo * sC2);
    __half* Ch = (__half*)Cv + ((long)zhi * sC1 + (long)zlo * sC2);

    const int m0 = blockIdx.y * BM;
    const int n0 = blockIdx.x * BN;
    if (CAUSAL == 1 && n0 > m0 + BM - 1) return;
    int Keff = K;
    if (CAUSAL == 2) Keff = min(K, m0 + BM);

    const int tid  = threadIdx.x;
    const int warp = tid >> 5;
    const int lane = tid & 31;
    const int gid  = lane >> 2;
    const int tig  = lane & 3;
    const int wm0  = (warp & 1) * 64;
    const int wn0  = (warp >> 1) * (BN / 4);

    const uint32_t lrow  = ((lane >> 3) & 1) * 8 + (lane & 7);
    const uint32_t chsel = (lane >> 4);       // k-half: 8 fp16 = one 16B chunk
    const uint32_t swl   = lane & 7;
    const uint32_t aRow = (wm0 + lrow) * 128;
    const uint32_t bRow = (wn0 + lrow) * 128;

    int ar[LA]; uint32_t ad[LA]; int aco[LA];
    #pragma unroll
    for (int i = 0; i < LA; i++) {
        int f = tid + i * 256, row = f >> 3, ch = f & 7;
        ar[i] = row; aco[i] = ch * 8;
        ad[i] = row * 128 + ((ch ^ (row & 7)) << 4);
    }
    int br[LB]; uint32_t bd[LB]; int bco[LB];
    #pragma unroll
    for (int i = 0; i < LB; i++) {
        int f = tid + i * 256, row = f >> 3, ch = f & 7;
        br[i] = row; bco[i] = ch * 8;
        bd[i] = BM * 128 + row * 128 + ((ch ^ (row & 7)) << 4);
    }

    float acc[MT][NT][4];
    #pragma unroll
    for (int i = 0; i < MT; i++)
        #pragma unroll
        for (int j = 0; j < NT; j++)
            #pragma unroll
            for (int r = 0; r < 4; r++) acc[i][j][r] = 0.f;

    const int T = Keff / BK;

    auto issue_stage = [&](int t) {
        const int k0 = t * BK;
        const uint32_t sb = smu + (t % STAGES) * STG_B;
        #pragma unroll
        for (int i = 0; i < LA; i++)
            cp16(sb + ad[i], &A[(long)(m0 + ar[i]) * lda + k0 + aco[i]]);
        #pragma unroll
        for (int i = 0; i < LB; i++)
            cp16(sb + bd[i], &B[(long)(n0 + br[i]) * ldb + k0 + bco[i]]);
        asm volatile("cp.async.commit_group;" ::: "memory");
    };

    int fetch = 0;
    #pragma unroll
    for (int s = 0; s < STAGES - 1; s++)
        if (fetch < T) { issue_stage(fetch); fetch++; }

    for (int t = 0; t < T; t++) {
        if (t == T - 1)
            asm volatile("cp.async.wait_group 0;" ::: "memory");
        else
            asm volatile("cp.async.wait_group %0;" :: "n"(STAGES - 2) : "memory");
        __syncthreads();
        if (fetch < T) { issue_stage(fetch); fetch++; }

        const uint32_t sb  = smu + (t % STAGES) * STG_B;
        const uint32_t sbB = sb + BM * 128;
        #pragma unroll
        for (int ks = 0; ks < 4; ks++) {          // 4 k16-steps per BK=64
            const uint32_t chx = (((2u * ks + chsel) ^ swl) << 4);
            unsigned a[MT][4];
            #pragma unroll
            for (int mt = 0; mt < MT; mt++)
                ldm_x4(a[mt][0], a[mt][1], a[mt][2], a[mt][3],
                       sb + aRow + mt * 16 * 128 + chx);
            unsigned b[NT][2];
            #pragma unroll
            for (int ng = 0; ng < NG; ng++) {
                unsigned q0, q1, q2, q3;
                ldm_x4(q0, q1, q2, q3, sbB + bRow + ng * 16 * 128 + chx);
                b[2*ng  ][0] = q0; b[2*ng  ][1] = q2;
                b[2*ng+1][0] = q1; b[2*ng+1][1] = q3;
            }
            #pragma unroll
            for (int mt = 0; mt < MT; mt++)
                #pragma unroll
                for (int nt = 0; nt < NT; nt++)
                    mma_f16(acc[mt][nt], a[mt], b[nt]);
        }
    }

    #pragma unroll
    for (int mt = 0; mt < MT; mt++) {
        int r0 = m0 + wm0 + mt * 16 + gid;
        #pragma unroll
        for (int nt = 0; nt < NT; nt++) {
            int cc = n0 + wn0 + nt * 8 + tig * 2;
            float o0 = acc[mt][nt][0] * alpha, o1 = acc[mt][nt][1] * alpha;
            float o2 = acc[mt][nt][2] * alpha, o3 = acc[mt][nt][3] * alpha;
            if (HOUT) {
                if (CT) {
                    Ch[(long)(cc    ) * ldc + r0    ] = __float2half_rn(o0);
                    Ch[(long)(cc + 1) * ldc + r0    ] = __float2half_rn(o1);
                    Ch[(long)(cc    ) * ldc + r0 + 8] = __float2half_rn(o2);
                    Ch[(long)(cc + 1) * ldc + r0 + 8] = __float2half_rn(o3);
                } else {
                    *(__half2*)&Ch[(long)r0 * ldc + cc]       = __floats2half2_rn(o0, o1);
                    *(__half2*)&Ch[(long)(r0 + 8) * ldc + cc] = __floats2half2_rn(o2, o3);
                }
            } else {
                if (CT) {
                    Cf[(long)(cc    ) * ldc + r0    ] = o0;
                    Cf[(long)(cc + 1) * ldc + r0    ] = o1;
                    Cf[(long)(cc    ) * ldc + r0 + 8] = o2;
                    Cf[(long)(cc + 1) * ldc + r0 + 8] = o3;
                } else {
                    *(float2*)&Cf[(long)r0 * ldc + cc]       = make_float2(o0, o1);
                    *(float2*)&Cf[(long)(r0 + 8) * ldc + cc] = make_float2(o2, o3);
                }
            }
        }
    }
}

// ---------------- elementwise fp16 convert ----------------------------------------
__global__ __launch_bounds__(256)
void cvt_h(const float4* __restrict__ in, __half2* __restrict__ out, int n4)
{
    int i = blockIdx.x * 256 + threadIdx.x;
    if (i < n4) {
        float4 v = in[i];
        out[2*i]   = __floats2half2_rn(v.x, v.y);
        out[2*i+1] = __floats2half2_rn(v.z, v.w);
    }
}

// ---------------- transpose + fp16 convert:  out[c*R + r] = h(in[r*C + c]) --------
__global__ __launch_bounds__(256)
void trcvt_h(const float* __restrict__ in, __half* __restrict__ out, int R, int C)
{
    __shared__ float t[32][33];
    const int r0 = blockIdx.y * 32, c0 = blockIdx.x * 32;
    const int tx = threadIdx.x & 31, ty = threadIdx.x >> 5;
    #pragma unroll
    for (int j = 0; j < 32; j += 8)
        t[ty + j][tx] = in[(long)(r0 + ty + j) * C + c0 + tx];
    __syncthreads();
    #pragma unroll
    for (int j = 0; j < 32; j += 8)
        out[(long)(c0 + ty + j) * R + r0 + tx] = __float2half_rn(t[tx][ty + j]);
}

// ---------------- LayerNorm over L=512 ------------------------------------------
__global__ __launch_bounds__(256)
void ln_k(const float* __restrict__ c, __half* __restrict__ ckv,
          float* __restrict__ out2,
          const float* __restrict__ gamma, const float* __restrict__ beta)
{
    __shared__ float red[256];
    const int r   = blockIdx.x;
    const int tid = threadIdx.x;
    const float* row = c + (long)r * L_;

    float a0 = row[tid], a1 = row[tid + 256];

    red[tid] = a0 + a1; __syncthreads();
    for (int s = 128; s > 0; s >>= 1) { if (tid < s) red[tid] += red[tid+s]; __syncthreads(); }
    float mu = red[0] * (1.0f / L_); __syncthreads();

    float d0 = a0 - mu, d1 = a1 - mu;
    red[tid] = d0*d0 + d1*d1; __syncthreads();
    for (int s = 128; s > 0; s >>= 1) { if (tid < s) red[tid] += red[tid+s]; __syncthreads(); }
    float rstd = rsqrtf(red[0] * (1.0f / L_) + 1e-5f);

    float y0 = d0 * rstd * gamma[tid]       + beta[tid];
    float y1 = d1 * rstd * gamma[tid + 256] + beta[tid + 256];

    long o = (long)r * L_;
    ckv[o + tid]       = __float2half_rn(y0);
    ckv[o + tid + 256] = __float2half_rn(y1);
    if (out2) { out2[o + tid] = y0; out2[o + tid + 256] = y1; }
}

// ---------------- causal softmax: fp32 scores -> fp16 attn -----------------------
// Zero-fills t in (s, round_up(s+1,128)) so the causally-clamped PV GEMM
// (Keff = multiple of 128) reads zeros past the diagonal.
__global__ __launch_bounds__(256)
void softmax_k(const float* __restrict__ sc, __half* __restrict__ at)
{
    __shared__ float red[256];
    const long r  = blockIdx.x;
    const int  s  = (int)(r % S_);
    const int tid = threadIdx.x;
    const float* row = sc + r * (long)S_;
    __half* orow = at + r * (long)S_;

    float v[8];
    float mx = -INFINITY;
    #pragma unroll
    for (int i = 0; i < 8; i++) {
        int t = tid + i*256;
        v[i] = (t <= s) ? row[t] : -INFINITY;
        mx = fmaxf(mx, v[i]);
    }
    red[tid] = mx; __syncthreads();
    for (int k = 128; k > 0; k >>= 1) { if (tid < k) red[tid] = fmaxf(red[tid], red[tid+k]); __syncthreads(); }
    mx = red[0]; __syncthreads();

    float sum = 0.f;
    #pragma unroll
    for (int i = 0; i < 8; i++) {
        int t = tid + i*256;
        v[i] = (t <= s) ? __expf(v[i] - mx) : 0.f;
        sum += v[i];
    }
    red[tid] = sum; __syncthreads();
    for (int k = 128; k > 0; k >>= 1) { if (tid < k) red[tid] += red[tid+k]; __syncthreads(); }
    float inv = 1.0f / red[0];

    const int bound = ((s >> 7) + 1) << 7;
    #pragma unroll
    for (int i = 0; i < 8; i++) {
        int t = tid + i*256;
        if (t < bound) orow[t] = __float2half_rn((t <= s) ? v[i] * inv : 0.f);
    }
}

// ---------------- launch ---------------------------------------------------------
extern "C" void kernel_launch(void* const* d_in, const int* in_sizes, int n_in,
                              void* d_out, int out_size)
{
    const float* x      = (const float*)d_in[0];
    const float* W_q    = (const float*)d_in[1];
    const float* W_dkv  = (const float*)d_in[2];
    const float* W_uk   = (const float*)d_in[3];
    const float* W_uv   = (const float*)d_in[4];
    const float* W_o    = (const float*)d_in[5];
    const float* gamma  = (const float*)d_in[6];
    const float* beta   = (const float*)d_in[7];
    float* out = (float*)d_out;

    float *c, *sc;
    __half *at, *ckv, *akT, *tmp, *vT, *ctx, *xh, *wdkv, *wq, *wukT, *wuv, *wo;
    cudaGetSymbolAddress((void**)&c,    g_c);
    cudaGetSymbolAddress((void**)&sc,   g_sc);
    cudaGetSymbolAddress((void**)&at,   g_at);
    cudaGetSymbolAddress((void**)&ckv,  g_ckv);
    cudaGetSymbolAddress((void**)&akT,  g_akT);
    cudaGetSymbolAddress((void**)&tmp,  g_tmp);
    cudaGetSymbolAddress((void**)&vT,   g_vT);
    cudaGetSymbolAddress((void**)&ctx,  g_ctx);
    cudaGetSymbolAddress((void**)&xh,   g_xh);
    cudaGetSymbolAddress((void**)&wdkv, g_wdkv);
    cudaGetSymbolAddress((void**)&wq,   g_wq);
    cudaGetSymbolAddress((void**)&wukT, g_wukT);
    cudaGetSymbolAddress((void**)&wuv,  g_wuv);
    cudaGetSymbolAddress((void**)&wo,   g_wo);

    float* out_ckv = (out_size >= NTOK*D_ + NTOK*L_) ? out + (long)NTOK*D_ : nullptr;

    const int SM128 = 3 * (128 + 128) * 128;   // 98304 B
    const int SM64  = 3 * (128 + 64)  * 128;   // 73728 B
    cudaFuncSetAttribute(hgemm<128,0,false,false>, cudaFuncAttributeMaxDynamicSharedMemorySize, SM128);
    cudaFuncSetAttribute(hgemm<128,0,true ,true >, cudaFuncAttributeMaxDynamicSharedMemorySize, SM128);
    cudaFuncSetAttribute(hgemm<128,0,false,true >, cudaFuncAttributeMaxDynamicSharedMemorySize, SM128);
    cudaFuncSetAttribute(hgemm<128,1,false,false>, cudaFuncAttributeMaxDynamicSharedMemorySize, SM128);
    cudaFuncSetAttribute(hgemm<64 ,2,false,true >, cudaFuncAttributeMaxDynamicSharedMemorySize, SM64);

    const dim3 blk(256);

    // P0: convert inputs to fp16
    cvt_h<<<NTOK*D_/1024, 256>>>((const float4*)x,     (__half2*)xh,   NTOK*D_/4);
    cvt_h<<<L_*D_/1024,   256>>>((const float4*)W_dkv, (__half2*)wdkv, L_*D_/4);
    cvt_h<<<D_*D_/1024,   256>>>((const float4*)W_q,   (__half2*)wq,   D_*D_/4);
    cvt_h<<<D_*L_/1024,   256>>>((const float4*)W_uv,  (__half2*)wuv,  D_*L_/4);
    cvt_h<<<D_*D_/1024,   256>>>((const float4*)W_o,   (__half2*)wo,   D_*D_/4);
    trcvt_h<<<dim3(L_/32, D_/32), 256>>>(W_uk, wukT, D_, L_);

    // K1: c = x @ W_dkv^T  (fp32 out -> LN)
    hgemm<128,0,false,false><<<dim3(L_/128, NTOK/128, 1), blk, SM128>>>(
        xh, wdkv, c, NTOK, L_, D_, D_, D_, L_,
        0,0, 0,0, 0,0, 16, 1.0f);

    // K2: LayerNorm -> ckv (fp16) + exact second output
    ln_k<<<NTOK, 256>>>(c, ckv, out_ckv, gamma, beta);

    // K3: akT = (W_q @ W_uk)^T  [L,D] fp16 (CT store)
    hgemm<128,0,true,true><<<dim3(L_/128, D_/128, 1), blk, SM128>>>(
        wq, wukT, akT, D_, L_, D_, D_, D_, D_,
        0,0, 0,0, 0,0, 16, 1.0f);

    // K4: tmp = q_eff (batched over h), K=64
    hgemm<128,0,false,true><<<dim3(L_/128, NTOK/128, H_), blk, SM128>>>(
        xh, akT, tmp, NTOK, L_, DH_, D_, D_, HL_,
        0, DH_,
        0, DH_,
        0, L_,
        16, 1.0f);

    // K5: scores = tmp @ ckv^T / 8  (batched b,h; causal block skip; fp32 out)
    hgemm<128,1,false,false><<<dim3(S_/128, S_/128, B_*H_), blk, SM128>>>(
        tmp, ckv, sc, S_, S_, L_, HL_, L_, S_,
        (long)S_*HL_,   (long)L_,
        (long)S_*L_,    0,
        (long)H_*S_*S_, (long)S_*S_,
        H_, 0.125f);

    // K6: causal softmax -> fp16 attn
    softmax_k<<<B_*H_*S_, 256>>>(sc, at);

    // K7: vT = (ckv @ W_uv^T)^T  [D,NTOK] fp16 (CT store)
    hgemm<128,0,true,true><<<dim3(D_/128, NTOK/128, 1), blk, SM128>>>(
        ckv, wuv, vT, NTOK, D_, L_, L_, L_, NTOK,
        0,0, 0,0, 0,0, 16, 1.0f);

    // K8: ctx = attn @ vT^T  (batched b,h; K causally clamped), fp16 out
    hgemm<64,2,false,true><<<dim3(1, S_/128, B_*H_), blk, SM64>>>(
        at, vT, ctx, S_, DH_, S_, S_, NTOK, D_,
        (long)H_*S_*S_, (long)S_*S_,
        (long)S_,       (long)DH_*NTOK,
        (long)S_*D_,    (long)DH_,
        H_, 1.0f);

    // K9: out = ctx @ W_o^T  (fp32 out)
    hgemm<128,0,false,false><<<dim3(D_/128, NTOK/128, 1), blk, SM128>>>(
        ctx, wo, out, NTOK, D_, D_, D_, D_, D_,
        0,0, 0,0, 0,0, 16, 1.0f);
}